// round 2
// baseline (speedup 1.0000x reference)
#include <cuda_runtime.h>

#define NANCH 8732
#define NCLS  599
#define MC    300
#define CAP   4096
#define ROWD  604

typedef unsigned int u32;
typedef unsigned long long u64;

// ------------------- static device scratch (no allocations) -------------------
__device__ float g_scoresT[2u * NCLS * NANCH];   // [B, C, N] transposed scores (~42MB)
__device__ u32   g_clsmax[2 * NCLS];             // per-class max score bits
__device__ u64   g_tkey[2];                      // global cutoff key per image
__device__ u64   g_key[2 * CAP];                 // compacted kept keys
__device__ u32   g_aux[2 * CAP];                 // anchor ids parallel to g_key
__device__ u32   g_cnt[2];                       // per-image append counters

// ------------------------------- reset ---------------------------------------
__global__ void k_reset() {
    int t = blockIdx.x * blockDim.x + threadIdx.x;
    if (t < 2) g_cnt[t] = 0;
    if (t < 2 * NCLS) g_clsmax[t] = 0;
}

// -------------------- transpose scores + per-class max -----------------------
__global__ void k_transpose(const float* __restrict__ in) {
    __shared__ float t[32][33];
    int b  = blockIdx.z;
    int n0 = blockIdx.x * 32;
    int c0 = blockIdx.y * 32;
    int tx = threadIdx.x, ty = threadIdx.y;

    // read: anchor = n0+ty, class = c0+tx  (consecutive tx -> consecutive cols, coalesced)
    int n = n0 + ty, c = c0 + tx;
    float v = 0.f;
    if (n < NANCH && c < NCLS)
        v = in[((size_t)b * NANCH + n) * ROWD + 1 + c];
    t[ty][tx] = v;
    __syncthreads();

    // write: class = c0+ty, anchor = n0+tx (coalesced)
    int cw = c0 + ty, nw = n0 + tx;
    if (cw < NCLS && nw < NANCH)
        g_scoresT[((size_t)b * NCLS + cw) * NANCH + nw] = t[tx][ty];

    // per-class max over this tile's 32 anchors: warp ty handles class c0+ty
    float m = t[tx][ty];   // value(anchor=n0+tx, class=c0+ty); stride-33 -> conflict-free
    #pragma unroll
    for (int off = 16; off; off >>= 1)
        m = fmaxf(m, __shfl_down_sync(0xffffffffu, m, off));
    if (tx == 0 && c0 + ty < NCLS)
        atomicMax(&g_clsmax[b * NCLS + c0 + ty], __float_as_uint(m));
}

// ------------- per-image cutoff = 200th largest class-max key ----------------
__global__ void k_thresh() {
    __shared__ u64 a[1024];
    int b = blockIdx.x, t = threadIdx.x;
    u64 v = 0;
    if (t < NCLS) {
        u32 mb = g_clsmax[b * NCLS + t];
        if (__uint_as_float(mb) > 0.01f)
            v = ((u64)mb << 32) | (u32)(~(u32)(t * MC));   // flat index of rank-0 = c*300
    }
    a[t] = v;
    __syncthreads();
    for (int k = 2; k <= 1024; k <<= 1)
        for (int j = k >> 1; j; j >>= 1) {
            int i = t, x = i ^ j;
            if (x > i) {
                u64 p = a[i], q = a[x];
                bool sw = ((i & k) == 0) ? (p < q) : (p > q);   // descending
                if (sw) { a[i] = q; a[x] = p; }
            }
            __syncthreads();
        }
    if (t == 0) g_tkey[b] = a[199];
}

// --------------- per-(b,c): top-300 select, NMS, filtered append --------------
__global__ void __launch_bounds__(512, 1) k_perclass(const float* __restrict__ in) {
    __shared__ u32 hist[256], suf[256];
    __shared__ u64 cand[512];
    __shared__ float4 sbox[MC];
    __shared__ float sarea[MC];
    __shared__ u32 ssup[MC * 10];
    __shared__ u32 keepw[10];
    __shared__ u32 s_cnt, s_cut, s_rem;
    __shared__ u64 s_tkey;

    int c = blockIdx.x, b = blockIdx.y;
    int tid = threadIdx.x, lane = tid & 31;

    const float* sc = &g_scoresT[((size_t)b * NCLS + c) * NANCH];
    u32 ub[18];
    #pragma unroll
    for (int e = 0; e < 18; e++) {
        int idx = e * 512 + tid;
        float s = (idx < NANCH) ? sc[idx] : 0.f;
        ub[e] = (s > 0.01f) ? __float_as_uint(s) : 0u;   // invalid -> key 0
    }
    if (tid == 0) { s_cnt = 0; s_tkey = g_tkey[b]; }

    // ---- 4-pass radix select: cutoff = 300th largest 32-bit key ----
    u32 prefix = 0, remain = MC;
    for (int pass = 0; pass < 4; pass++) {
        int shift = 24 - 8 * pass;
        if (tid < 256) hist[tid] = 0;
        __syncthreads();
        #pragma unroll
        for (int e = 0; e < 18; e++) {
            u32 u = ub[e];
            bool part = (pass == 0) || ((u >> (shift + 8)) == prefix);
            int bin = (u >> shift) & 0xFF;
            int key = part ? bin : 256;
            u32 grp = __match_any_sync(0xffffffffu, key);   // warp-aggregate same-bin
            if (part && lane == (__ffs(grp) - 1))
                atomicAdd(&hist[bin], __popc(grp));
        }
        __syncthreads();
        if (tid < 256) suf[tid] = hist[tid];
        __syncthreads();
        for (int off = 1; off < 256; off <<= 1) {           // suffix sums
            u32 add = (tid < 256 && tid + off < 256) ? suf[tid + off] : 0;
            __syncthreads();
            if (tid < 256) suf[tid] += add;
            __syncthreads();
        }
        if (tid == 0) { s_cut = 0; s_rem = remain - suf[1]; }  // shortfall default
        __syncthreads();
        if (tid < 256) {
            u32 above = (tid == 255) ? 0u : suf[tid + 1];
            if (suf[tid] >= remain && above < remain) { s_cut = (u32)tid; s_rem = remain - above; }
        }
        __syncthreads();
        prefix = (prefix << 8) | s_cut;
        remain = s_rem;
        __syncthreads();
    }

    // ---- collect candidates: strictly greater + equals (equals sorted by idx later) ----
    #pragma unroll
    for (int e = 0; e < 18; e++) {
        u32 u = ub[e];
        if (u > prefix || (u == prefix && prefix != 0)) {
            u32 pos = atomicAdd(&s_cnt, 1);
            if (pos < 512)
                cand[pos] = ((u64)u << 32) | (u32)(~(u32)(e * 512 + tid));
        }
    }
    __syncthreads();
    u32 cnt = min(s_cnt, 512u);
    if ((u32)tid >= cnt) cand[tid] = 0;
    __syncthreads();

    // ---- bitonic sort 512 desc (key embeds ~anchor -> stable top_k semantics) ----
    for (int k = 2; k <= 512; k <<= 1)
        for (int j = k >> 1; j; j >>= 1) {
            int i = tid, x = i ^ j;
            if (x > i) {
                u64 p = cand[i], q = cand[x];
                bool sw = ((i & k) == 0) ? (p < q) : (p > q);
                if (sw) { cand[i] = q; cand[x] = p; }
            }
            __syncthreads();
        }
    int M = min((int)cnt, MC);

    // ---- box gather + corner encode (exact reference fp sequence) ----
    float y0i = 0, x0i = 0, y1i = 0, x1i = 0, ai = 0;
    u32 anchor = 0, ubits = 0;
    if (tid < M) {
        u64 key = cand[tid];
        ubits  = (u32)(key >> 32);
        anchor = ~(u32)key;
        const float4 bx = *(const float4*)(in + ((size_t)b * NANCH + anchor) * ROWD + 600);
        // bx = (cx, cy, w, h)
        y0i = __fsub_rn(bx.y, __fmul_rn(bx.w, 0.5f));
        x0i = __fsub_rn(bx.x, __fmul_rn(bx.z, 0.5f));
        y1i = __fadd_rn(bx.y, __fmul_rn(bx.w, 0.5f));
        x1i = __fadd_rn(bx.x, __fmul_rn(bx.z, 0.5f));
        ai  = __fmul_rn(__fsub_rn(y1i, y0i), __fsub_rn(x1i, x0i));
        sbox[tid]  = make_float4(y0i, x0i, y1i, x1i);   // (y0, x0, y1, x1)
        sarea[tid] = ai;
    }
    __syncthreads();

    // ---- suppression bitmask rows (j < i only); broadcast LDS per inner step ----
    if (tid < M) {
        #pragma unroll
        for (int w = 0; w < 10; w++) {
            u32 m = 0;
            for (int jj = 0; jj < 32; jj++) {
                int j = w * 32 + jj;
                if (j < tid) {
                    float4 bj = sbox[j];
                    float aj  = sarea[j];
                    float ih = fmaxf(__fsub_rn(fminf(y1i, bj.z), fmaxf(y0i, bj.x)), 0.f);
                    float iw = fmaxf(__fsub_rn(fminf(x1i, bj.w), fmaxf(x0i, bj.y)), 0.f);
                    float inter = __fmul_rn(ih, iw);
                    float uni   = __fsub_rn(__fadd_rn(ai, aj), inter);
                    bool sup = (uni > 0.f) && (__fdiv_rn(inter, uni) > 0.45f);
                    m |= ((u32)sup) << jj;
                }
            }
            ssup[tid * 10 + w] = m;
        }
    }
    __syncthreads();

    // ---- serial greedy on warp 0: lanes 0..9 hold kept-bitset words ----
    if (tid < 32) {
        u32 kreg = 0;
        for (int i = 0; i < M; i++) {
            u32 row = (lane < 10) ? ssup[i * 10 + lane] : 0u;
            bool any = __any_sync(0xffffffffu, (kreg & row) != 0u);
            if (!any && lane == (i >> 5)) kreg |= 1u << (i & 31);
        }
        if (lane < 10) keepw[lane] = kreg;
    }
    __syncthreads();

    // ---- append kept candidates above the provably-safe global cutoff ----
    if (tid < M) {
        if ((keepw[tid >> 5] >> (tid & 31)) & 1u) {
            u64 gkey = ((u64)ubits << 32) | (u32)(~(u32)(c * MC + tid));
            if (gkey >= s_tkey) {
                u32 pos = atomicAdd(&g_cnt[b], 1u);
                if (pos < CAP) { g_key[b * CAP + pos] = gkey; g_aux[b * CAP + pos] = anchor; }
            }
        }
    }
}

// --------------------- final: top-200 by key, re-encode ----------------------
__global__ void __launch_bounds__(1024, 1) k_final(const float* __restrict__ in,
                                                   float* __restrict__ out) {
    __shared__ u64 skey[2048];
    __shared__ u32 saux[2048];
    int b = blockIdx.x, t = threadIdx.x;
    u32 n = min(min(g_cnt[b], (u32)CAP), 2048u);
    #pragma unroll
    for (int r = 0; r < 2; r++) {
        int i = t + r * 1024;
        if ((u32)i < n) { skey[i] = g_key[b * CAP + i]; saux[i] = g_aux[b * CAP + i]; }
        else            { skey[i] = 0;                  saux[i] = 0; }
    }
    __syncthreads();
    for (int k = 2; k <= 2048; k <<= 1)
        for (int j = k >> 1; j; j >>= 1) {
            #pragma unroll
            for (int r = 0; r < 2; r++) {
                int i = t + r * 1024, x = i ^ j;
                if (x > i) {
                    u64 p = skey[i], q = skey[x];
                    bool sw = ((i & k) == 0) ? (p < q) : (p > q);
                    if (sw) {
                        skey[i] = q; skey[x] = p;
                        u32 ap = saux[i]; saux[i] = saux[x]; saux[x] = ap;
                    }
                }
            }
            __syncthreads();
        }

    if (t < 200) {
        u64 key = skey[t];
        float cls = 0.f, score = 0.f, ocx = 0.f, ocy = 0.f, otw = 0.f, oth = 0.f;
        if (key) {
            score = __uint_as_float((u32)(key >> 32));
            u32 flat = ~(u32)key;
            cls = (float)(flat / MC + 1);
            u32 anchor = saux[t];
            const float4 bx = *(const float4*)(in + ((size_t)b * NANCH + anchor) * ROWD + 600);
            float y0 = __fsub_rn(bx.y, __fmul_rn(bx.w, 0.5f));
            float x0 = __fsub_rn(bx.x, __fmul_rn(bx.z, 0.5f));
            float y1 = __fadd_rn(bx.y, __fmul_rn(bx.w, 0.5f));
            float x1 = __fadd_rn(bx.x, __fmul_rn(bx.z, 0.5f));
            otw = __fsub_rn(x1, x0);
            oth = __fsub_rn(y1, y0);
            ocx = __fadd_rn(x0, __fmul_rn(otw, 0.5f));
            ocy = __fadd_rn(y0, __fmul_rn(oth, 0.5f));
        }
        float* o = out + ((size_t)b * 200 + t) * 6;
        o[0] = cls; o[1] = score; o[2] = ocx; o[3] = ocy; o[4] = otw; o[5] = oth;
    }
}

// ------------------------------------------------------------------------------
extern "C" void kernel_launch(void* const* d_in, const int* in_sizes, int n_in,
                              void* d_out, int out_size) {
    const float* in = (const float*)d_in[0];
    float* out = (float*)d_out;

    k_reset<<<2, 1024>>>();
    dim3 tb(32, 32);
    dim3 tg((NANCH + 31) / 32, (NCLS + 31) / 32, 2);
    k_transpose<<<tg, tb>>>(in);
    k_thresh<<<2, 1024>>>();
    k_perclass<<<dim3(NCLS, 2), 512>>>(in);
    k_final<<<2, 1024>>>(in, out);
}

// round 3
// speedup vs baseline: 1.6239x; 1.6239x over previous
#include <cuda_runtime.h>

#define NANCH 8732
#define NCLS  599
#define MC    300
#define CAP   4096
#define ROWD  604

typedef unsigned int u32;
typedef unsigned long long u64;

// ------------------- static device scratch (no allocations) -------------------
__device__ float g_scoresT[2u * NCLS * NANCH];   // [B, C, N] transposed scores
__device__ u32   g_clsmax[2 * NCLS];             // per-class max score bits
__device__ u64   g_tkey[2];                      // global cutoff key per image
__device__ u64   g_key[2 * CAP];                 // compacted kept keys
__device__ u32   g_aux[2 * CAP];                 // anchor ids parallel to g_key
__device__ u32   g_cnt[2];                       // per-image append counters

// ------------------------------- reset ---------------------------------------
__global__ void k_reset() {
    int t = blockIdx.x * blockDim.x + threadIdx.x;
    if (t < 2) g_cnt[t] = 0;
    if (t < 2 * NCLS) g_clsmax[t] = 0;
}

// -------------------- transpose scores + per-class max -----------------------
// tile: 128 anchors x 32 classes, 256 threads
__global__ void __launch_bounds__(256) k_transpose(const float* __restrict__ in) {
    __shared__ float t[128][33];
    int b  = blockIdx.z;
    int n0 = blockIdx.x * 128;
    int c0 = blockIdx.y * 32;
    int tid = threadIdx.x, lane = tid & 31, w = tid >> 5;

    // load: warp w loads anchor rows w, w+8, ... ; lanes span 32 classes (coalesced)
    #pragma unroll
    for (int r = 0; r < 16; r++) {
        int nl = w + r * 8;
        int n = n0 + nl, c = c0 + lane;
        float v = 0.f;
        if (n < NANCH && c < NCLS)
            v = __ldg(&in[((size_t)b * NANCH + n) * ROWD + 1 + c]);
        t[nl][lane] = v;                       // addr stride 1 across lanes: no conflict
    }
    __syncthreads();

    // store: warp w handles classes w, w+8, w+16, w+24; lanes span anchors (coalesced)
    #pragma unroll
    for (int r = 0; r < 4; r++) {
        int cl = w + r * 8;
        int c  = c0 + cl;
        float mx = 0.f;
        if (c < NCLS) {
            float* dst = &g_scoresT[((size_t)b * NCLS + c) * NANCH];
            #pragma unroll
            for (int k2 = 0; k2 < 4; k2++) {
                int nl = lane + 32 * k2;       // addr stride 33 across lanes: no conflict
                int n = n0 + nl;
                if (n < NANCH) {
                    float v = t[nl][cl];
                    dst[n] = v;
                    mx = fmaxf(mx, v);
                }
            }
        }
        #pragma unroll
        for (int off = 16; off; off >>= 1)
            mx = fmaxf(mx, __shfl_xor_sync(0xffffffffu, mx, off));
        if (lane == 0 && c < NCLS)
            atomicMax(&g_clsmax[b * NCLS + c], __float_as_uint(mx));
    }
}

// ------------- per-image cutoff = 200th largest class-max key ----------------
__global__ void k_thresh() {
    __shared__ u64 a[1024];
    int b = blockIdx.x, t = threadIdx.x;
    u64 v = 0;
    if (t < NCLS) {
        u32 mb = g_clsmax[b * NCLS + t];
        if (__uint_as_float(mb) > 0.01f)
            v = ((u64)mb << 32) | (u32)(~(u32)(t * MC));
    }
    a[t] = v;
    __syncthreads();
    for (int k = 2; k <= 1024; k <<= 1)
        for (int j = k >> 1; j; j >>= 1) {
            int i = t, x = i ^ j;
            if (x > i) {
                u64 p = a[i], q = a[x];
                bool sw = ((i & k) == 0) ? (p < q) : (p > q);
                if (sw) { a[i] = q; a[x] = p; }
            }
            __syncthreads();
        }
    if (t == 0) g_tkey[b] = a[199];
}

// --------------- per-(b,c): top-300 select, NMS, filtered append --------------
__global__ void __launch_bounds__(512, 3) k_perclass(const float* __restrict__ in) {
    __shared__ __align__(16) char buf[9216 * 4];   // scores, later aliased by NMS state
    __shared__ u32 hist[256], suf[256];
    __shared__ u64 cand[512];
    __shared__ u32 s_cnt, s_cut, s_ge, s_above;
    __shared__ u64 s_tkey;

    int c = blockIdx.x, b = blockIdx.y;
    int tid = threadIdx.x, lane = tid & 31, wid = tid >> 5;

    u32* ssc = (u32*)buf;
    const float* sc = &g_scoresT[((size_t)b * NCLS + c) * NANCH];

    // ---- stage masked score bits to smem (zero-padded to 9216) ----
    #pragma unroll
    for (int e = 0; e < 18; e++) {
        int i = e * 512 + tid;
        u32 v = 0;
        if (i < NANCH) {
            float s = sc[i];
            v = (s > 0.01f) ? __float_as_uint(s) : 0u;
        }
        ssc[i] = v;
    }
    if (tid == 0) { s_cnt = 0; s_tkey = g_tkey[b]; }

    // ---- radix select with early exit: find thresh s.t. count(u>=thresh, u!=0) in [min(300,valid), 512] ----
    u32 prefix = 0, remain = MC, thresh = 0;
    for (int pass = 0; pass < 4; pass++) {
        int shift = 24 - 8 * pass;
        if (tid < 256) hist[tid] = 0;
        __syncthreads();                       // covers staging on pass 0
        #pragma unroll
        for (int e = 0; e < 18; e++) {
            u32 u = ssc[e * 512 + tid];
            bool part = (pass == 0) || ((u >> (shift + 8)) == prefix);
            int bin = (u >> shift) & 0xFF;
            int key = part ? bin : 999;
            u32 grp = __match_any_sync(0xffffffffu, key);
            if (part && lane == (u32)(__ffs(grp) - 1))
                atomicAdd(&hist[bin], __popc(grp));
        }
        __syncthreads();
        if (tid < 256) suf[tid] = hist[tid];
        __syncthreads();
        for (int off = 1; off < 256; off <<= 1) {   // suffix sums
            u32 add = (tid < 256 && tid + off < 256) ? suf[tid + off] : 0;
            __syncthreads();
            if (tid < 256) suf[tid] += add;
            __syncthreads();
        }
        if (tid == 0) { s_cut = 0; s_ge = suf[0]; s_above = 0; }  // shortfall default
        __syncthreads();
        if (tid < 256) {
            u32 ge = suf[tid];
            u32 ab = (tid == 255) ? 0u : suf[tid + 1];
            if (ge >= remain && ab < remain) { s_cut = (u32)tid; s_ge = ge; s_above = ab; }
        }
        __syncthreads();
        u32 total_ge = (MC - remain) + s_ge;   // count(u >= candidate thresh)
        thresh = ((prefix << 8) | s_cut) << shift;
        if (total_ge <= 512 || pass == 3) break;
        prefix = (prefix << 8) | s_cut;
        remain -= s_above;
        __syncthreads();
    }

    // ---- collect superset, key = (score_bits<<32) | ~anchor (stable top_k ties) ----
    #pragma unroll
    for (int e = 0; e < 18; e++) {
        u32 u = ssc[e * 512 + tid];
        if (u >= thresh && u != 0) {
            u32 pos = atomicAdd(&s_cnt, 1);
            if (pos < 512)
                cand[pos] = ((u64)u << 32) | (u32)(~(u32)(e * 512 + tid));
        }
    }
    __syncthreads();
    u32 cnt = min(s_cnt, 512u);
    if ((u32)tid >= cnt) cand[tid] = 0;
    __syncthreads();

    // ---- bitonic sort 512 desc ----
    for (int k = 2; k <= 512; k <<= 1)
        for (int j = k >> 1; j; j >>= 1) {
            int i = tid, x = i ^ j;
            if (x > i) {
                u64 p = cand[i], q = cand[x];
                bool sw = ((i & k) == 0) ? (p < q) : (p > q);
                if (sw) { cand[i] = q; cand[x] = p; }
            }
            __syncthreads();
        }
    int M = min((int)cnt, MC);

    // ---- NMS state aliases the dead score buffer ----
    float4* sbox  = (float4*)buf;              // [300] : 0..4800
    float*  sarea = (float*)(buf + 4800);      // [300] : 4800..6000
    u32*    aw    = (u32*)(buf + 6016);        // [2][10] alive ballot words

    float y0i = 0, x0i = 0, y1i = 0, x1i = 0, ai = 0;
    u32 anchor = 0, ubits = 0;
    bool alive = tid < M;
    if (alive) {
        u64 key = cand[tid];
        ubits  = (u32)(key >> 32);
        anchor = ~(u32)key;
        const float4 bx = *(const float4*)(in + ((size_t)b * NANCH + anchor) * ROWD + 600);
        // bx = (cx, cy, w, h) -> exact reference corner encode
        y0i = __fsub_rn(bx.y, __fmul_rn(bx.w, 0.5f));
        x0i = __fsub_rn(bx.x, __fmul_rn(bx.z, 0.5f));
        y1i = __fadd_rn(bx.y, __fmul_rn(bx.w, 0.5f));
        x1i = __fadd_rn(bx.x, __fmul_rn(bx.z, 0.5f));
        ai  = __fmul_rn(__fsub_rn(y1i, y0i), __fsub_rn(x1i, x0i));
        sbox[tid]  = make_float4(y0i, x0i, y1i, x1i);
        sarea[tid] = ai;
    }

    // ---- parallel frontier greedy: one round per KEPT box ----
    bool kept = false;
    u32 bw = __ballot_sync(0xffffffffu, alive);
    if (lane == 0 && wid < 10) aw[wid] = bw;
    __syncthreads();                            // also publishes sbox/sarea
    int i = -1;
    #pragma unroll
    for (int w2 = 0; w2 < 10; w2++) {
        u32 x = aw[w2];
        if (x) { i = w2 * 32 + (__ffs(x) - 1); break; }
    }
    int par = 1;
    while (i >= 0) {
        float4 bi = sbox[i];                    // broadcast LDS
        float  aK = sarea[i];
        if (alive) {
            if (tid == i) { kept = true; alive = false; }
            else {
                float ih = fmaxf(__fsub_rn(fminf(y1i, bi.z), fmaxf(y0i, bi.x)), 0.f);
                float iw = fmaxf(__fsub_rn(fminf(x1i, bi.w), fmaxf(x0i, bi.y)), 0.f);
                float inter = __fmul_rn(ih, iw);
                float uni   = __fsub_rn(__fadd_rn(ai, aK), inter);
                if (uni > 0.f && __fdiv_rn(inter, uni) > 0.45f) alive = false;
            }
        }
        bw = __ballot_sync(0xffffffffu, alive);
        if (lane == 0 && wid < 10) aw[par * 10 + wid] = bw;
        __syncthreads();
        i = -1;
        int base = par * 10;
        #pragma unroll
        for (int w2 = 0; w2 < 10; w2++) {
            u32 x = aw[base + w2];
            if (x) { i = w2 * 32 + (__ffs(x) - 1); break; }
        }
        par ^= 1;
    }

    // ---- append kept candidates above the provably-safe global cutoff ----
    if (kept) {
        u64 gkey = ((u64)ubits << 32) | (u32)(~(u32)(c * MC + tid));
        if (gkey >= s_tkey) {
            u32 pos = atomicAdd(&g_cnt[b], 1u);
            if (pos < CAP) { g_key[b * CAP + pos] = gkey; g_aux[b * CAP + pos] = anchor; }
        }
    }
}

// --------------------- final: top-200 by key, re-encode ----------------------
__global__ void __launch_bounds__(1024, 1) k_final(const float* __restrict__ in,
                                                   float* __restrict__ out) {
    __shared__ u64 skey[2048];
    __shared__ u32 saux[2048];
    int b = blockIdx.x, t = threadIdx.x;
    u32 n = min(min(g_cnt[b], (u32)CAP), 2048u);
    #pragma unroll
    for (int r = 0; r < 2; r++) {
        int i = t + r * 1024;
        if ((u32)i < n) { skey[i] = g_key[b * CAP + i]; saux[i] = g_aux[b * CAP + i]; }
        else            { skey[i] = 0;                  saux[i] = 0; }
    }
    __syncthreads();
    for (int k = 2; k <= 2048; k <<= 1)
        for (int j = k >> 1; j; j >>= 1) {
            #pragma unroll
            for (int r = 0; r < 2; r++) {
                int i = t + r * 1024, x = i ^ j;
                if (x > i) {
                    u64 p = skey[i], q = skey[x];
                    bool sw = ((i & k) == 0) ? (p < q) : (p > q);
                    if (sw) {
                        skey[i] = q; skey[x] = p;
                        u32 ap = saux[i]; saux[i] = saux[x]; saux[x] = ap;
                    }
                }
            }
            __syncthreads();
        }

    if (t < 200) {
        u64 key = skey[t];
        float cls = 0.f, score = 0.f, ocx = 0.f, ocy = 0.f, otw = 0.f, oth = 0.f;
        if (key) {
            score = __uint_as_float((u32)(key >> 32));
            u32 flat = ~(u32)key;
            cls = (float)(flat / MC + 1);
            u32 anchor = saux[t];
            const float4 bx = *(const float4*)(in + ((size_t)b * NANCH + anchor) * ROWD + 600);
            float y0 = __fsub_rn(bx.y, __fmul_rn(bx.w, 0.5f));
            float x0 = __fsub_rn(bx.x, __fmul_rn(bx.z, 0.5f));
            float y1 = __fadd_rn(bx.y, __fmul_rn(bx.w, 0.5f));
            float x1 = __fadd_rn(bx.x, __fmul_rn(bx.z, 0.5f));
            otw = __fsub_rn(x1, x0);
            oth = __fsub_rn(y1, y0);
            ocx = __fadd_rn(x0, __fmul_rn(otw, 0.5f));
            ocy = __fadd_rn(y0, __fmul_rn(oth, 0.5f));
        }
        float* o = out + ((size_t)b * 200 + t) * 6;
        o[0] = cls; o[1] = score; o[2] = ocx; o[3] = ocy; o[4] = otw; o[5] = oth;
    }
}

// ------------------------------------------------------------------------------
extern "C" void kernel_launch(void* const* d_in, const int* in_sizes, int n_in,
                              void* d_out, int out_size) {
    const float* in = (const float*)d_in[0];
    float* out = (float*)d_out;

    k_reset<<<2, 1024>>>();
    dim3 tg((NANCH + 127) / 128, (NCLS + 31) / 32, 2);
    k_transpose<<<tg, 256>>>(in);
    k_thresh<<<2, 1024>>>();
    k_perclass<<<dim3(NCLS, 2), 512>>>(in);
    k_final<<<2, 1024>>>(in, out);
}

// round 4
// speedup vs baseline: 2.6505x; 1.6322x over previous
#include <cuda_runtime.h>

#define NANCH 8732
#define NCLS  599
#define MC    300
#define CAP   4096
#define ROWD  604

typedef unsigned int u32;
typedef unsigned long long u64;

// ------------------- static device scratch (no allocations) -------------------
__device__ u32   g_clsmax[2 * NCLS];             // per-class max score bits
__device__ u64   g_tkey[2];                      // global cutoff key per image
__device__ u64   g_key[2 * CAP];                 // compacted kept keys
__device__ u32   g_aux[2 * CAP];                 // anchor ids parallel to g_key
__device__ u32   g_cnt[2];                       // per-image append counters

// ------------------------------- reset ---------------------------------------
__global__ void k_reset() {
    int t = blockIdx.x * blockDim.x + threadIdx.x;
    if (t < 2) g_cnt[t] = 0;
    if (t < 2 * NCLS) g_clsmax[t] = 0;
}

// ---------------- per-class max (coalesced scan of input, warms L2) ----------
__global__ void __launch_bounds__(256) k_clsmax(const float* __restrict__ in) {
    int b  = blockIdx.y;
    int a0 = blockIdx.x * 69;                    // 128 chunks x 69 >= 8732
    int a1 = min(a0 + 69, NANCH);
    int t  = threadIdx.x;
    float m0 = 0.f, m1 = 0.f, m2 = 0.f;
    for (int a = a0; a < a1; a++) {
        const float* row = in + ((size_t)b * NANCH + a) * ROWD + 1;
        m0 = fmaxf(m0, __ldg(&row[t]));
        if (t + 256 < NCLS) m1 = fmaxf(m1, __ldg(&row[t + 256]));
        if (t + 512 < NCLS) m2 = fmaxf(m2, __ldg(&row[t + 512]));
    }
    atomicMax(&g_clsmax[b * NCLS + t], __float_as_uint(m0));
    if (t + 256 < NCLS) atomicMax(&g_clsmax[b * NCLS + t + 256], __float_as_uint(m1));
    if (t + 512 < NCLS) atomicMax(&g_clsmax[b * NCLS + t + 512], __float_as_uint(m2));
}

// ------------- per-image cutoff = 200th largest class-max key ----------------
__global__ void k_thresh() {
    __shared__ u64 a[1024];
    int b = blockIdx.x, t = threadIdx.x;
    u64 v = 0;
    if (t < NCLS) {
        u32 mb = g_clsmax[b * NCLS + t];
        if (__uint_as_float(mb) > 0.01f)
            v = ((u64)mb << 32) | (u32)(~(u32)(t * MC));
    }
    a[t] = v;
    __syncthreads();
    for (int k = 2; k <= 1024; k <<= 1)
        for (int j = k >> 1; j; j >>= 1) {
            int i = t, x = i ^ j;
            if (x > i) {
                u64 p = a[i], q = a[x];
                bool sw = ((i & k) == 0) ? (p < q) : (p > q);
                if (sw) { a[i] = q; a[x] = p; }
            }
            __syncthreads();
        }
    if (t == 0) g_tkey[b] = a[199];
}

// -------- exact IoU>0.45 predicate with guarded div-free fast path -----------
__device__ __forceinline__ bool iou_gt(float y0, float x0, float y1, float x1, float a,
                                       float4 bj, float aj) {
    float ih = fmaxf(__fsub_rn(fminf(y1, bj.z), fmaxf(y0, bj.x)), 0.f);
    float iw = fmaxf(__fsub_rn(fminf(x1, bj.w), fmaxf(x0, bj.y)), 0.f);
    float inter = __fmul_rn(ih, iw);
    float uni   = __fsub_rn(__fadd_rn(a, aj), inter);
    if (!(uni > 0.f)) return false;
    float t = __fmul_rn(uni, 0.45f);
    if (inter > __fmul_rn(t, 1.000002f)) return true;    // safely above boundary
    if (inter < __fmul_rn(t, 0.999998f)) return false;   // safely below
    return __fdiv_rn(inter, uni) > 0.45f;                // exact (rare)
}

// --------------- per-(b,c): top-300 select, NMS, filtered append --------------
__global__ void __launch_bounds__(512, 4) k_perclass(const float* __restrict__ in) {
    __shared__ __align__(16) char buf[9216 * 4];   // scores, later aliased by NMS boxes
    __shared__ u32 hist[256], suf[256];
    __shared__ u64 cand[512];
    __shared__ float4 tbox[32];
    __shared__ float  tarea[32];
    __shared__ u32    tsup[32];
    __shared__ u32    wcnt[16];
    __shared__ u32 s_cnt, s_cut, s_ge, s_above, s_kmask;
    __shared__ u64 s_tkey;

    int c = blockIdx.x, b = blockIdx.y;
    int tid = threadIdx.x, lane = tid & 31, wid = tid >> 5;

    u32* ssc = (u32*)buf;
    const float* sc = in + (size_t)b * NANCH * ROWD + 1 + c;

    // ---- stage masked score bits straight from input (strided, L2-resident) ----
    #pragma unroll
    for (int e = 0; e < 18; e++) {
        int i = e * 512 + tid;
        u32 v = 0;
        if (i < NANCH) {
            float s = __ldg(&sc[(size_t)i * ROWD]);
            v = (s > 0.01f) ? __float_as_uint(s) : 0u;
        }
        ssc[i] = v;
    }
    if (tid == 0) { s_cnt = 0; s_tkey = g_tkey[b]; }

    // ---- radix select, early exit when superset fits in 512 ----
    u32 prefix = 0, remain = MC, thresh = 0;
    for (int pass = 0; pass < 4; pass++) {
        int shift = 24 - 8 * pass;
        if (tid < 256) hist[tid] = 0;
        __syncthreads();
        #pragma unroll
        for (int e = 0; e < 18; e++) {
            u32 u = ssc[e * 512 + tid];
            bool part = (pass == 0) || ((u >> (shift + 8)) == prefix);
            int bin = (u >> shift) & 0xFF;
            int key = part ? bin : 999;
            u32 grp = __match_any_sync(0xffffffffu, key);
            if (part && lane == (u32)(__ffs(grp) - 1))
                atomicAdd(&hist[bin], __popc(grp));
        }
        __syncthreads();
        if (tid < 256) suf[tid] = hist[tid];
        __syncthreads();
        for (int off = 1; off < 256; off <<= 1) {
            u32 add = (tid < 256 && tid + off < 256) ? suf[tid + off] : 0;
            __syncthreads();
            if (tid < 256) suf[tid] += add;
            __syncthreads();
        }
        if (tid == 0) { s_cut = 0; s_ge = suf[0]; s_above = 0; }
        __syncthreads();
        if (tid < 256) {
            u32 ge = suf[tid];
            u32 ab = (tid == 255) ? 0u : suf[tid + 1];
            if (ge >= remain && ab < remain) { s_cut = (u32)tid; s_ge = ge; s_above = ab; }
        }
        __syncthreads();
        u32 total_ge = (MC - remain) + s_ge;
        thresh = ((prefix << 8) | s_cut) << shift;
        if (total_ge <= 512 || pass == 3) break;
        prefix = (prefix << 8) | s_cut;
        remain -= s_above;
        __syncthreads();
    }

    // ---- collect superset, key = (score_bits<<32) | ~anchor ----
    #pragma unroll
    for (int e = 0; e < 18; e++) {
        u32 u = ssc[e * 512 + tid];
        if (u >= thresh && u != 0) {
            u32 pos = atomicAdd(&s_cnt, 1);
            if (pos < 512)
                cand[pos] = ((u64)u << 32) | (u32)(~(u32)(e * 512 + tid));
        }
    }
    __syncthreads();
    u32 cnt = min(s_cnt, 512u);
    if ((u32)tid >= cnt) cand[tid] = 0;
    __syncthreads();

    // ---- bitonic sort 512 desc ----
    for (int k = 2; k <= 512; k <<= 1)
        for (int j = k >> 1; j; j >>= 1) {
            int i = tid, x = i ^ j;
            if (x > i) {
                u64 p = cand[i], q = cand[x];
                bool sw = ((i & k) == 0) ? (p < q) : (p > q);
                if (sw) { cand[i] = q; cand[x] = p; }
            }
            __syncthreads();
        }
    int M = min((int)cnt, MC);

    // ---- per-thread box (exact reference corner encode) ----
    float y0i = 0, x0i = 0, y1i = 0, x1i = 0, ai = 0;
    u32 anchor = 0, ubits = 0;
    bool alive = tid < M;
    if (alive) {
        u64 key = cand[tid];
        ubits  = (u32)(key >> 32);
        anchor = ~(u32)key;
        const float4 bx = *(const float4*)(in + ((size_t)b * NANCH + anchor) * ROWD + 600);
        // bx = (cx, cy, w, h)
        y0i = __fsub_rn(bx.y, __fmul_rn(bx.w, 0.5f));
        x0i = __fsub_rn(bx.x, __fmul_rn(bx.z, 0.5f));
        y1i = __fadd_rn(bx.y, __fmul_rn(bx.w, 0.5f));
        x1i = __fadd_rn(bx.x, __fmul_rn(bx.z, 0.5f));
        ai  = __fmul_rn(__fsub_rn(y1i, y0i), __fsub_rn(x1i, x0i));
    }

    // ---- tile-speculative greedy NMS: 32 candidates finalized per round ----
    bool kept = false;
    while (true) {
        // 1. per-warp alive ballots
        u32 wb = __ballot_sync(0xffffffffu, alive);
        if (lane == 0) wcnt[wid] = wb;
        __syncthreads();
        // 2. total alive + my rank among alive (sorted order == tid order)
        int total = 0, before = 0;
        #pragma unroll
        for (int w = 0; w < 16; w++) {
            int p = __popc(wcnt[w]);
            total += p;
            if (w < wid) before += p;
        }
        if (total == 0) break;
        int rank = before + __popc(wb & ((1u << lane) - 1u));
        bool intile = alive && rank < 32;
        int nt = min(total, 32);
        if (intile) {
            tbox[rank]  = make_float4(y0i, x0i, y1i, x1i);
            tarea[rank] = ai;
        }
        __syncthreads();
        // 3. speculative suppression mask vs tile members (no barriers inside)
        u32 msup = 0;
        if (alive) {
            for (int j = 0; j < nt; j++) {
                bool s = iou_gt(y0i, x0i, y1i, x1i, ai, tbox[j], tarea[j]);
                msup |= ((u32)s) << j;
            }
        }
        if (intile) tsup[rank] = msup & ((1u << rank) - 1u);
        __syncthreads();
        // 4. serial in-tile greedy (one thread, 32 steps)
        if (tid == 0) {
            u32 km = 0;
            for (int k = 0; k < nt; k++)
                if ((tsup[k] & km) == 0u) km |= 1u << k;
            s_kmask = km;
        }
        __syncthreads();
        // 5. apply: tile members finalize; others die if suppressed by a kept member
        u32 km = s_kmask;
        if (intile) { kept = (km >> rank) & 1u; alive = false; }
        else if (alive && (msup & km)) alive = false;
        __syncthreads();
    }

    // ---- append kept candidates above the provably-safe global cutoff ----
    if (kept) {
        u64 gkey = ((u64)ubits << 32) | (u32)(~(u32)(c * MC + tid));
        if (gkey >= s_tkey) {
            u32 pos = atomicAdd(&g_cnt[b], 1u);
            if (pos < CAP) { g_key[b * CAP + pos] = gkey; g_aux[b * CAP + pos] = anchor; }
        }
    }
}

// --------------------- final: top-200 by key, re-encode ----------------------
__global__ void __launch_bounds__(1024, 1) k_final(const float* __restrict__ in,
                                                   float* __restrict__ out) {
    __shared__ u64 skey[2048];
    __shared__ u32 saux[2048];
    int b = blockIdx.x, t = threadIdx.x;
    u32 n = min(min(g_cnt[b], (u32)CAP), 2048u);
    #pragma unroll
    for (int r = 0; r < 2; r++) {
        int i = t + r * 1024;
        if ((u32)i < n) { skey[i] = g_key[b * CAP + i]; saux[i] = g_aux[b * CAP + i]; }
        else            { skey[i] = 0;                  saux[i] = 0; }
    }
    __syncthreads();
    for (int k = 2; k <= 2048; k <<= 1)
        for (int j = k >> 1; j; j >>= 1) {
            #pragma unroll
            for (int r = 0; r < 2; r++) {
                int i = t + r * 1024, x = i ^ j;
                if (x > i) {
                    u64 p = skey[i], q = skey[x];
                    bool sw = ((i & k) == 0) ? (p < q) : (p > q);
                    if (sw) {
                        skey[i] = q; skey[x] = p;
                        u32 ap = saux[i]; saux[i] = saux[x]; saux[x] = ap;
                    }
                }
            }
            __syncthreads();
        }

    if (t < 200) {
        u64 key = skey[t];
        float cls = 0.f, score = 0.f, ocx = 0.f, ocy = 0.f, otw = 0.f, oth = 0.f;
        if (key) {
            score = __uint_as_float((u32)(key >> 32));
            u32 flat = ~(u32)key;
            cls = (float)(flat / MC + 1);
            u32 anchor = saux[t];
            const float4 bx = *(const float4*)(in + ((size_t)b * NANCH + anchor) * ROWD + 600);
            float y0 = __fsub_rn(bx.y, __fmul_rn(bx.w, 0.5f));
            float x0 = __fsub_rn(bx.x, __fmul_rn(bx.z, 0.5f));
            float y1 = __fadd_rn(bx.y, __fmul_rn(bx.w, 0.5f));
            float x1 = __fadd_rn(bx.x, __fmul_rn(bx.z, 0.5f));
            otw = __fsub_rn(x1, x0);
            oth = __fsub_rn(y1, y0);
            ocx = __fadd_rn(x0, __fmul_rn(otw, 0.5f));
            ocy = __fadd_rn(y0, __fmul_rn(oth, 0.5f));
        }
        float* o = out + ((size_t)b * 200 + t) * 6;
        o[0] = cls; o[1] = score; o[2] = ocx; o[3] = ocy; o[4] = otw; o[5] = oth;
    }
}

// ------------------------------------------------------------------------------
extern "C" void kernel_launch(void* const* d_in, const int* in_sizes, int n_in,
                              void* d_out, int out_size) {
    const float* in = (const float*)d_in[0];
    float* out = (float*)d_out;

    k_reset<<<2, 1024>>>();
    k_clsmax<<<dim3(128, 2), 256>>>(in);
    k_thresh<<<2, 1024>>>();
    k_perclass<<<dim3(NCLS, 2), 512>>>(in);
    k_final<<<2, 1024>>>(in, out);
}